// round 9
// baseline (speedup 1.0000x reference)
#include <cuda_runtime.h>
#include <cstddef>
#include <cstdint>

#define NP 4
#define NS 4
#define NC 64
#define NF 64
#define NB 64
// PS = 16, PSC = 1024

__device__ float g_weights[NP * NS * NC * NC];   // softmax(scores), 256 KB
__device__ int   g_wcount[NP * NS];              // per-ps completion counters

// packed fp32x2 FMA: {d.lo,d.hi} += {a.lo*b.lo, a.hi*b.hi} — exact fp32, 2x rate
__device__ __forceinline__ void ffma2(unsigned long long& acc,
                                      unsigned long long a,
                                      unsigned long long b) {
    asm("fma.rn.f32x2 %0, %1, %2, %0;" : "+l"(acc) : "l"(a), "l"(b));
}
__device__ __forceinline__ unsigned long long dup2(float w) {
    unsigned long long r;
    asm("mov.b64 %0, {%1, %1};" : "=l"(r) : "f"(w));
    return r;
}

// ---------------------------------------------------------------------------
__global__ void reset_kernel() {
    if (threadIdx.x < NP * NS) g_wcount[threadIdx.x] = 0;
}

// ---------------------------------------------------------------------------
// Single fused kernel, 2048 blocks x 1024 threads, PRODUCERS-FIRST ordering
// (the R6 interleave put spinning consumers resident from wave 0 and killed
//  the DRAM stream; bid-ordered dispatch fixes it):
//
// bids 0..1023   (producers): psc = bid (ps-major). KQ reduction at the DRAM
//   roofline + fused softmax; fence + atomicAdd on g_wcount[ps].
//   Waves 0-3.5 are 100% producers -> full DRAM residency.
// bids 1024..2047 (consumers): idx = bid-1024; ps = idx>>6, b = idx&63.
//   By the time a consumer becomes resident (wave >= 3.5), its ps group of
//   producers has long finished -> ~zero spin. GEMM1 (V into smem, no gmem
//   round-trip), check counter, GEMM2 -> out. All consumer compute hides in
//   the second-half idle issue slots; the tail is just the last ps group.
// Deadlock-free: 1024 consumers < dispatch ordering guarantees producers all
//   dispatched first, and producers never wait.
// ---------------------------------------------------------------------------
__global__ void __launch_bounds__(1024, 2)
fused_all_kernel(const float* __restrict__ kq,
                 const float* __restrict__ x,
                 const float* __restrict__ wv,
                 float* __restrict__ out) {
    __shared__ float sh[NC * (NF + 1) + NC * (NF + 4)];  // 34 KB union

    const int bid = blockIdx.x;
    const int t   = threadIdx.x;

    if (bid < NP * NS * NC) {
        // ================= producers: KQ reduction + softmax ==============
        const int psc = bid;
        const int ps  = psc >> 6;
        const int d   = t >> 4;
        const int j   = t & 15;

        const float4* base =
            reinterpret_cast<const float4*>(kq + (size_t)psc * (NF * NC * NF))
            + (d * (NF / 4) + j);

        float4 acc = make_float4(0.f, 0.f, 0.f, 0.f);
#pragma unroll 4
        for (int f = 0; f < NF; ++f) {
            float4 v = __ldcs(base + f * (NC * NF / 4));
            acc.x += v.x; acc.y += v.y; acc.z += v.z; acc.w += v.w;
        }
        float s = (acc.x + acc.y) + (acc.z + acc.w);

        s += __shfl_xor_sync(0xffffffffu, s, 8);
        s += __shfl_xor_sync(0xffffffffu, s, 4);
        s += __shfl_xor_sync(0xffffffffu, s, 2);
        s += __shfl_xor_sync(0xffffffffu, s, 1);

        if (j == 0) sh[d] = s;
        __syncthreads();

        if (t < 32) {
            const float a = sh[t];
            const float b = sh[t + 32];
            float m = fmaxf(a, b);
#pragma unroll
            for (int off = 16; off > 0; off >>= 1)
                m = fmaxf(m, __shfl_xor_sync(0xffffffffu, m, off));
            const float ea = __expf(a - m);
            const float eb = __expf(b - m);
            float ssum = ea + eb;
#pragma unroll
            for (int off = 16; off > 0; off >>= 1)
                ssum += __shfl_xor_sync(0xffffffffu, ssum, off);
            const float inv = 1.0f / ssum;
            g_weights[psc * NC + t]      = ea * inv;
            g_weights[psc * NC + t + 32] = eb * inv;
            __threadfence();               // publish weights before counting
            __syncwarp();
            if (t == 0) atomicAdd(&g_wcount[ps], 1);
        }
    } else {
        // ====== consumers: GEMM1 (V in smem) + brief wait + GEMM2 =========
        const int idx = bid - NP * NS * NC;
        const int ps  = idx >> 6;          // matches producer finishing order
        const int b   = idx & 63;
        const int bp  = b * (NP * NS) + ps;

        float* bufX  = sh;                 // [64][65] : X[c][k]   (later V)
        float* bufWT = sh + NC * (NF + 1); // [64][68] : Wv^T[k][f] (later w)

        // ---- load X tile (coalesced) + Wv transposed ----
        const float* xsrc = x + (size_t)bp * (NC * NF);
#pragma unroll
        for (int r = 0; r < 4; ++r) {
            const int i  = t + r * 1024;
            const int hi = i >> 6, lo = i & 63;
            bufX[hi * (NF + 1) + lo]  = xsrc[i];
            bufWT[lo * (NF + 4) + hi] = wv[i];     // wv[f][k] -> WT[k][f]
        }
        __syncthreads();

        // ---- GEMM1: V[c][4fq..] = sum_k X[c][k] * WvT[k][4fq..] ----
        const int c  = t >> 4;
        const int fq = t & 15;
        float4 vacc = make_float4(0.f, 0.f, 0.f, 0.f);
#pragma unroll 8
        for (int k = 0; k < NF; ++k) {
            const float  xk = bufX[c * (NF + 1) + k];
            const float4 w4 = *reinterpret_cast<const float4*>(
                                  &bufWT[k * (NF + 4) + 4 * fq]);
            vacc.x += xk * w4.x; vacc.y += xk * w4.y;
            vacc.z += xk * w4.z; vacc.w += xk * w4.w;
        }
        __syncthreads();   // all GEMM1 reads done before overwriting buffers

        // ---- V into smem (bufX region, flat [64][64]) ----
        float* bufV = sh;
        *reinterpret_cast<float4*>(&bufV[c * NF + 4 * fq]) = vacc;

        // ---- wait for this ps's weights (normally already done) ----
        if (t == 0) {
            while (*((volatile int*)&g_wcount[ps]) < NC) __nanosleep(128);
            __threadfence();
        }
        __syncthreads();

        // ---- load weights[ps] into bufWT region as w[c][d], stride 68 ----
        float* bufW = sh + NC * (NF + 1);
        const float4* wsrc = reinterpret_cast<const float4*>(
                                 g_weights + (size_t)ps * (NC * NC));
        {
            const float4 wv4 = wsrc[t];            // 1024 float4 = whole tile
            reinterpret_cast<float4*>(&bufW[(t >> 4) * (NF + 4)])[t & 15] = wv4;
        }
        __syncthreads();

        // ---- GEMM2: out[c][4fq..] = sum_d w[c][d] * V[d][4fq..] ----
        unsigned long long o01 = 0ull, o23 = 0ull;
        const int frow = 4 * fq;
#pragma unroll 4
        for (int d4 = 0; d4 < NC / 4; ++d4) {
            const ulonglong2 v0 = *reinterpret_cast<const ulonglong2*>(&bufV[(4 * d4 + 0) * NF + frow]);
            const ulonglong2 v1 = *reinterpret_cast<const ulonglong2*>(&bufV[(4 * d4 + 1) * NF + frow]);
            const ulonglong2 v2 = *reinterpret_cast<const ulonglong2*>(&bufV[(4 * d4 + 2) * NF + frow]);
            const ulonglong2 v3 = *reinterpret_cast<const ulonglong2*>(&bufV[(4 * d4 + 3) * NF + frow]);
            const float4 w4 = *reinterpret_cast<const float4*>(
                                  &bufW[c * (NF + 4) + 4 * d4]);   // broadcast
            const unsigned long long wx = dup2(w4.x);
            const unsigned long long wy = dup2(w4.y);
            const unsigned long long wz = dup2(w4.z);
            const unsigned long long ww = dup2(w4.w);
            ffma2(o01, wx, v0.x);  ffma2(o23, wx, v0.y);
            ffma2(o01, wy, v1.x);  ffma2(o23, wy, v1.y);
            ffma2(o01, wz, v2.x);  ffma2(o23, wz, v2.y);
            ffma2(o01, ww, v3.x);  ffma2(o23, ww, v3.y);
        }

        // ---- store: out[c, b, ps*F + f] (f-slice [frow, frow+4)) ----
        float* orow = out + ((size_t)c * NB + b) * (NP * NS * NF) + (size_t)ps * NF;
        float4 o;
        o.x = __uint_as_float((unsigned)(o01 & 0xffffffffull));
        o.y = __uint_as_float((unsigned)(o01 >> 32));
        o.z = __uint_as_float((unsigned)(o23 & 0xffffffffull));
        o.w = __uint_as_float((unsigned)(o23 >> 32));
        *reinterpret_cast<float4*>(&orow[frow]) = o;
    }
}

// ---------------------------------------------------------------------------
extern "C" void kernel_launch(void* const* d_in, const int* in_sizes, int n_in,
                              void* d_out, int out_size) {
    const float* X  = (const float*)d_in[0];  // (B, P*S*C*F)
    const float* KQ = (const float*)d_in[1];  // (P,S,C,F,C,F) — 1 GB
    const float* Wv = (const float*)d_in[2];  // (F, F)
    float* out = (float*)d_out;               // (C, B, P*S*F)

    reset_kernel<<<1, 32>>>();
    fused_all_kernel<<<2048, 1024>>>(KQ, X, Wv, out);
}

// round 10
// speedup vs baseline: 1.2555x; 1.2555x over previous
#include <cuda_runtime.h>
#include <cstddef>
#include <cstdint>

#define NP 4
#define NS 4
#define NC 64
#define NF 64
#define NB 64
// PS = 16, PSC = 1024, per-psc KQ block = F*C*F = 262144 floats

__device__ float g_weights[NP * NS * NC * NC];           // softmax(scores), 256 KB
__device__ float g_V[NB * NP * NS * NC * NF];            // V = X @ Wv^T, 16 MB

// packed fp32x2 FMA: {d.lo,d.hi} += {a.lo*b.lo, a.hi*b.hi} — exact fp32, 2x rate
__device__ __forceinline__ void ffma2(unsigned long long& acc,
                                      unsigned long long a,
                                      unsigned long long b) {
    asm("fma.rn.f32x2 %0, %1, %2, %0;" : "+l"(acc) : "l"(a), "l"(b));
}
// pack one fp32 into both lanes of a 64-bit pair (ALU pipe, 1 instr)
__device__ __forceinline__ unsigned long long dup2(float w) {
    unsigned long long r;
    asm("mov.b64 %0, {%1, %1};" : "=l"(r) : "f"(w));
    return r;
}

// ---------------------------------------------------------------------------
// Kernel 1 (unchanged, 89.5% of HBM spec): 2048 blocks x 1024 threads.
// EVEN blocks (psc = bid>>1): KQ reduction + fused softmax.
// ODD  blocks (bp  = bid>>1): V[bp] = X[bp] @ Wv^T in the idle issue slots.
// ---------------------------------------------------------------------------
__global__ void __launch_bounds__(1024, 2)
reduce_softmax_v_kernel(const float* __restrict__ kq,
                        const float* __restrict__ x,
                        const float* __restrict__ wv) {
    __shared__ float sh[NC * (NF + 1) + NC * (NF + 4)];  // 34 KB union

    const int bid = blockIdx.x;
    const int t   = threadIdx.x;

    if ((bid & 1) == 0) {
        // ---- role A: KQ reduction + softmax ----
        const int psc = bid >> 1;
        const int d   = t >> 4;
        const int j   = t & 15;

        const float4* base =
            reinterpret_cast<const float4*>(kq + (size_t)psc * (NF * NC * NF))
            + (d * (NF / 4) + j);

        float4 acc = make_float4(0.f, 0.f, 0.f, 0.f);
#pragma unroll 4
        for (int f = 0; f < NF; ++f) {
            float4 v = __ldcs(base + f * (NC * NF / 4));
            acc.x += v.x; acc.y += v.y; acc.z += v.z; acc.w += v.w;
        }
        float s = (acc.x + acc.y) + (acc.z + acc.w);

        s += __shfl_xor_sync(0xffffffffu, s, 8);
        s += __shfl_xor_sync(0xffffffffu, s, 4);
        s += __shfl_xor_sync(0xffffffffu, s, 2);
        s += __shfl_xor_sync(0xffffffffu, s, 1);

        if (j == 0) sh[d] = s;
        __syncthreads();

        if (t < 32) {
            const float a = sh[t];
            const float b = sh[t + 32];
            float m = fmaxf(a, b);
#pragma unroll
            for (int off = 16; off > 0; off >>= 1)
                m = fmaxf(m, __shfl_xor_sync(0xffffffffu, m, off));
            const float ea = __expf(a - m);
            const float eb = __expf(b - m);
            float ssum = ea + eb;
#pragma unroll
            for (int off = 16; off > 0; off >>= 1)
                ssum += __shfl_xor_sync(0xffffffffu, ssum, off);
            const float inv = 1.0f / ssum;
            g_weights[psc * NC + t]      = ea * inv;
            g_weights[psc * NC + t + 32] = eb * inv;
        }
    } else {
        // ---- role B: V = X @ Wv^T for one (b,ps), float4-vectorized ----
        const int bp = bid >> 1;                    // = b*16 + ps
        float* bufX  = sh;                          // [64][65] : X[c][k]
        float* bufWT = sh + NC * (NF + 1);          // [64][68] : Wv^T[k][f]

        const float* xsrc = x + (size_t)bp * (NC * NF);
#pragma unroll
        for (int r = 0; r < 4; ++r) {
            const int idx = t + r * 1024;
            const int hi  = idx >> 6, lo = idx & 63;
            bufX[hi * (NF + 1) + lo]  = xsrc[idx];
            bufWT[lo * (NF + 4) + hi] = wv[idx];    // wv[f][k] -> bufWT[k][f]
        }
        __syncthreads();

        const int c  = t >> 4;
        const int fq = t & 15;
        float4 acc = make_float4(0.f, 0.f, 0.f, 0.f);
#pragma unroll 8
        for (int k = 0; k < NF; ++k) {
            const float  xk = bufX[c * (NF + 1) + k];
            const float4 w4 = *reinterpret_cast<const float4*>(
                                  &bufWT[k * (NF + 4) + 4 * fq]);
            acc.x += xk * w4.x; acc.y += xk * w4.y;
            acc.z += xk * w4.z; acc.w += xk * w4.w;
        }

        float4* vdst = reinterpret_cast<float4*>(g_V + (size_t)bp * (NC * NF));
        vdst[c * (NF / 4) + fq] = acc;
    }
}

// ---------------------------------------------------------------------------
// Kernel 2: out[b,ps][c][f] = sum_d w[ps][c][d] * V[b,ps][d][f]
// 1024 blocks x 128 threads, 8c x 4f register tile.
// Thread (tcg = t>>4 in 0..7, tf = t&15): c in {tcg+8i}, f-slice [4tf,4tf+4).
// Per d4 chunk: 4 V LDS.128 (conflict-free, reused across 8 c -> half the
// crossbar traffic of the 4c tile) + 8 broadcast w LDS.128 + 64 FFMA2.
// 128-thread blocks -> ~6 resident/SM, 1024 blocks ~= 1 wave.
// ---------------------------------------------------------------------------
__global__ void __launch_bounds__(128)
attn_out_kernel(float* __restrict__ out) {
    __shared__ float bufV[NC * NF];         // V[d][f], flat, rows contiguous
    __shared__ float bufW[NC * (NF + 4)];   // w[c][d], stride 68 (16B-aligned)

    const int blk = blockIdx.x;
    const int b   = blk >> 4;
    const int ps  = blk & 15;
    const int t   = threadIdx.x;
    const int tcg = t >> 4;                 // 0..7
    const int tf  = t & 15;                 // 0..15

    const float4* vsrc = reinterpret_cast<const float4*>(g_V + (size_t)blk * (NC * NF));
    const float4* wsrc = reinterpret_cast<const float4*>(g_weights + (size_t)ps * (NC * NC));
    float4* bv4 = reinterpret_cast<float4*>(bufV);
#pragma unroll
    for (int r = 0; r < 8; ++r) {
        const int i4 = t + r * 128;                  // 0..1023 float4s
        bv4[i4] = vsrc[i4];
        reinterpret_cast<float4*>(&bufW[(i4 >> 4) * (NF + 4)])[i4 & 15] = wsrc[i4];
    }
    __syncthreads();

    unsigned long long o01[8], o23[8];   // per c-row: {f,f+1} and {f+2,f+3}
#pragma unroll
    for (int i = 0; i < 8; ++i) { o01[i] = 0ull; o23[i] = 0ull; }

    const int frow = 4 * tf;

#pragma unroll 4
    for (int d4 = 0; d4 < NC / 4; ++d4) {
        // V rows for d = 4*d4 .. 4*d4+3, f-slice [frow, frow+4) as u64 pairs
        const ulonglong2 v0 = *reinterpret_cast<const ulonglong2*>(&bufV[(4 * d4 + 0) * NF + frow]);
        const ulonglong2 v1 = *reinterpret_cast<const ulonglong2*>(&bufV[(4 * d4 + 1) * NF + frow]);
        const ulonglong2 v2 = *reinterpret_cast<const ulonglong2*>(&bufV[(4 * d4 + 2) * NF + frow]);
        const ulonglong2 v3 = *reinterpret_cast<const ulonglong2*>(&bufV[(4 * d4 + 3) * NF + frow]);

#pragma unroll
        for (int i = 0; i < 8; ++i) {
            // broadcast LDS.128: 2 distinct c addresses per warp
            const float4 w4 = *reinterpret_cast<const float4*>(
                                  &bufW[(tcg + 8 * i) * (NF + 4) + 4 * d4]);
            const unsigned long long wx = dup2(w4.x);
            const unsigned long long wy = dup2(w4.y);
            const unsigned long long wz = dup2(w4.z);
            const unsigned long long ww = dup2(w4.w);
            ffma2(o01[i], wx, v0.x);  ffma2(o23[i], wx, v0.y);
            ffma2(o01[i], wy, v1.x);  ffma2(o23[i], wy, v1.y);
            ffma2(o01[i], wz, v2.x);  ffma2(o23[i], wz, v2.y);
            ffma2(o01[i], ww, v3.x);  ffma2(o23[i], ww, v3.y);
        }
    }

    // out layout: (C, B, P*S*F); out[c, b, ps*F + f], f-slice [frow, frow+4)
#pragma unroll
    for (int i = 0; i < 8; ++i) {
        const int c = tcg + 8 * i;
        float* orow = out + ((size_t)c * NB + b) * (NP * NS * NF) + (size_t)ps * NF;
        float4 o;
        o.x = __uint_as_float((unsigned)(o01[i] & 0xffffffffull));
        o.y = __uint_as_float((unsigned)(o01[i] >> 32));
        o.z = __uint_as_float((unsigned)(o23[i] & 0xffffffffull));
        o.w = __uint_as_float((unsigned)(o23[i] >> 32));
        *reinterpret_cast<float4*>(&orow[frow]) = o;
    }
}

// ---------------------------------------------------------------------------
extern "C" void kernel_launch(void* const* d_in, const int* in_sizes, int n_in,
                              void* d_out, int out_size) {
    const float* X  = (const float*)d_in[0];  // (B, P*S*C*F)
    const float* KQ = (const float*)d_in[1];  // (P,S,C,F,C,F) — 1 GB
    const float* Wv = (const float*)d_in[2];  // (F, F)
    float* out = (float*)d_out;               // (C, B, P*S*F)

    reduce_softmax_v_kernel<<<2048, 1024>>>(KQ, X, Wv);
    attn_out_kernel<<<NB * NP * NS, 128>>>(out);
}